// round 9
// baseline (speedup 1.0000x reference)
#include <cuda_runtime.h>
#include <cuda_fp16.h>

// ---------------------------------------------------------------------------
// GINBlock: h = BN(relu( relu((x + segsum(x[src]->dst)) @ W1 + b1) @ W2 + b2 ))
// N=100000, D=H=128, E=3.2M.
// R9 (resubmit of R8; prior round died to container infra failure):
//     mega-fusion — aggregate + GEMM1 + GEMM2 + BN-stats in ONE kernel per
//     128-row tile (kills h0/h1 round trips, ~200MB). W pre-staged in GLOBAL
//     fragment order (coalesced L1-resident b-loads) so smem = A tile only
//     (66KB -> 2 CTAs/SM). Keep: fp16 mirror, CSR counting sort, tf32 MMA.
// ---------------------------------------------------------------------------

#define GIN_N_MAX 100000
#define GIN_H 128
#define GIN_E_MAX 3200000
#define SCAN_B 1024
#define SCAN_NB ((GIN_N_MAX + SCAN_B - 1) / SCAN_B)   // 98

__device__ __half   g_xh[GIN_N_MAX * GIN_H];     // fp16 mirror of x
__device__ int      g_deg[GIN_N_MAX];
__device__ int      g_off[GIN_N_MAX + 1];
__device__ int      g_cursor[GIN_N_MAX];
__device__ int      g_srcs[GIN_E_MAX];
__device__ int      g_bsum[SCAN_NB];
__device__ int      g_boff[SCAN_NB];
__device__ __align__(16) unsigned g_w1f[16384];  // W1 tf32, fragment order
__device__ __align__(16) unsigned g_w2f[16384];  // W2 tf32, fragment order
__device__ __align__(16) float g_sum[GIN_H];
__device__ __align__(16) float g_sq[GIN_H];
__device__ int      g_is64;

__device__ __forceinline__ unsigned f2tf(float f) {
    unsigned r;
    asm("cvt.rna.tf32.f32 %0, %1;" : "=r"(r) : "f"(f));
    return r;
}
__device__ __forceinline__ void mma_tf32(float* d, const unsigned* a, unsigned b0, unsigned b1) {
    asm("mma.sync.aligned.m16n8k8.row.col.f32.tf32.tf32.f32 "
        "{%0,%1,%2,%3}, {%4,%5,%6,%7}, {%8,%9}, {%0,%1,%2,%3};"
        : "+f"(d[0]), "+f"(d[1]), "+f"(d[2]), "+f"(d[3])
        : "r"(a[0]), "r"(a[1]), "r"(a[2]), "r"(a[3]), "r"(b0), "r"(b1));
}

// zero deg + BN accums; thread 0 sniffs int64-vs-int32 edge_index.
__global__ void zero_kernel(const unsigned* __restrict__ ei, int N) {
    int idx = blockIdx.x * blockDim.x + threadIdx.x;
    if (idx < N) g_deg[idx] = 0;
    if (idx < GIN_H) { g_sum[idx] = 0.f; g_sq[idx] = 0.f; }
    if (idx == 0) {
        int allz = 1;
#pragma unroll
        for (int i = 0; i < 16; i++) allz &= (ei[2 * i + 1] == 0u);
        g_is64 = allz;
    }
}

// fp32 x -> fp16 mirror
__global__ void convert_kernel(const float4* __restrict__ x4, int total4) {
    int idx = blockIdx.x * blockDim.x + threadIdx.x;
    if (idx >= total4) return;
    float4 v = x4[idx];
    __half2 a = __floats2half2_rn(v.x, v.y);
    __half2 b = __floats2half2_rn(v.z, v.w);
    uint2 p;
    p.x = *(unsigned*)&a;
    p.y = *(unsigned*)&b;
    ((uint2*)g_xh)[idx] = p;
}

// Build W1/W2 tf32 fragment-order arrays in global.
// slot s: lane=s&31, ntg=(s>>5)&15, ks=s>>9; b0=W[ks*8+l%4][ntg*8+l/4], b1=+4k.
__global__ void wprep_kernel(const float* __restrict__ W1,
                             const float* __restrict__ W2) {
    int s = blockIdx.x * blockDim.x + threadIdx.x;   // 0..8191
    if (s >= 8192) return;
    int l = s & 31, ntg = (s >> 5) & 15, ks = s >> 9;
    int k = ks * 8 + (l & 3);
    int n = ntg * 8 + (l >> 2);
    *(uint2*)&g_w1f[s * 2] = make_uint2(f2tf(__ldg(&W1[k * 128 + n])),
                                        f2tf(__ldg(&W1[(k + 4) * 128 + n])));
    *(uint2*)&g_w2f[s * 2] = make_uint2(f2tf(__ldg(&W2[k * 128 + n])),
                                        f2tf(__ldg(&W2[(k + 4) * 128 + n])));
}

__global__ void hist_kernel(const void* __restrict__ ei, int E) {
    int e = blockIdx.x * blockDim.x + threadIdx.x;
    if (e >= E) return;
    int d = g_is64 ? (int)__ldg(&((const long long*)ei)[E + e])
                   : __ldg(&((const int*)ei)[E + e]);
    atomicAdd(&g_deg[d], 1);
}

// ---- 3-phase exclusive scan ----
__global__ void __launch_bounds__(SCAN_B)
scan1_kernel(int N) {
    __shared__ int sh[SCAN_B];
    int t = threadIdx.x;
    int i = blockIdx.x * SCAN_B + t;
    int v = (i < N) ? g_deg[i] : 0;
    sh[t] = v;
    __syncthreads();
#pragma unroll
    for (int d = 1; d < SCAN_B; d <<= 1) {
        int u = (t >= d) ? sh[t - d] : 0;
        __syncthreads();
        sh[t] += u;
        __syncthreads();
    }
    if (i < N) g_off[i] = sh[t] - v;
    if (t == SCAN_B - 1) g_bsum[blockIdx.x] = sh[t];
}

__global__ void __launch_bounds__(128)
scan2_kernel(int NB) {
    __shared__ int sh[128];
    int t = threadIdx.x;
    int v = (t < NB) ? g_bsum[t] : 0;
    sh[t] = v;
    __syncthreads();
#pragma unroll
    for (int d = 1; d < 128; d <<= 1) {
        int u = (t >= d) ? sh[t - d] : 0;
        __syncthreads();
        sh[t] += u;
        __syncthreads();
    }
    if (t < NB) g_boff[t] = sh[t] - v;
}

__global__ void scan3_kernel(int N, int E) {
    int i = blockIdx.x * blockDim.x + threadIdx.x;
    if (i >= N) return;
    int v = g_off[i] + g_boff[i >> 10];
    g_off[i] = v;
    g_cursor[i] = v;
    if (i == 0) g_off[N] = E;
}

__global__ void permute_kernel(const void* __restrict__ ei, int E) {
    int e = blockIdx.x * blockDim.x + threadIdx.x;
    if (e >= E) return;
    int s, d;
    if (g_is64) {
        const long long* p = (const long long*)ei;
        s = (int)__ldg(&p[e]);
        d = (int)__ldg(&p[E + e]);
    } else {
        const int* p = (const int*)ei;
        s = __ldg(&p[e]);
        d = __ldg(&p[E + e]);
    }
    int pos = atomicAdd(&g_cursor[d], 1);
    g_srcs[pos] = s;
}

// ---------------------------------------------------------------------------
// FUSED: per 128-row tile: aggregate (CSR fp16 gather) -> As(tf32, stride 132)
//        -> GEMM1(+b1,relu) -> As -> GEMM2(+b2,relu) -> out + BN stats.
// 512 threads = 16 warps. Aggregation: warp w handles 8 nodes.
// GEMM: rg=wid>>1 (16-row group), cg=wid&1 (64-col group); warp tile 16x64.
// ---------------------------------------------------------------------------
#define AS_STRIDE 132
#define FUSED_SMEM (128 * AS_STRIDE * 4)     // 67584 B

__global__ void __launch_bounds__(512, 2)
fused_kernel(const float4* __restrict__ x4,
             const float* __restrict__ bias1,
             const float* __restrict__ bias2,
             float* __restrict__ out, int N) {
    extern __shared__ unsigned As[];         // [128][AS_STRIDE]
    const int tid = threadIdx.x;
    const int lane = tid & 31;
    const int wid = tid >> 5;
    const int row0 = blockIdx.x * 128;

    // ---- Phase 1: aggregation (8 nodes per warp) ----
    const uint2* xh = (const uint2*)g_xh;
    for (int rr = 0; rr < 8; rr++) {
        int r = wid * 8 + rr;
        int node = row0 + r;
        float4 acc = make_float4(0.f, 0.f, 0.f, 0.f);
        if (node < N) {
            acc = x4[node * 32 + lane];
            int e = g_off[node], end = g_off[node + 1];
            while (e < end) {
                int cnt = min(32, end - e);
                int myidx = (lane < cnt) ? __ldg(&g_srcs[e + lane]) : 0;
#pragma unroll 4
                for (int j = 0; j < cnt; j++) {
                    int s = __shfl_sync(0xffffffffu, myidx, j);
                    uint2 p = xh[s * 32 + lane];
                    float2 f01 = __half22float2(*(__half2*)&p.x);
                    float2 f23 = __half22float2(*(__half2*)&p.y);
                    acc.x += f01.x; acc.y += f01.y;
                    acc.z += f23.x; acc.w += f23.y;
                }
                e += cnt;
            }
        }
        *(uint4*)&As[r * AS_STRIDE + 4 * lane] =
            make_uint4(f2tf(acc.x), f2tf(acc.y), f2tf(acc.z), f2tf(acc.w));
    }
    __syncthreads();

    // ---- Phase 2: GEMM1 ----
    const int rg = wid >> 1, cg = wid & 1;
    float d[8][4];
#pragma unroll
    for (int nt = 0; nt < 8; nt++)
#pragma unroll
        for (int r = 0; r < 4; r++) d[nt][r] = 0.f;

    const int rbase = rg * 16 + (lane >> 2);
#pragma unroll
    for (int ksg = 0; ksg < 16; ksg++) {
        int k = ksg * 8 + (lane & 3);
        unsigned a[4];
        a[0] = As[rbase * AS_STRIDE + k];
        a[1] = As[(rbase + 8) * AS_STRIDE + k];
        a[2] = As[rbase * AS_STRIDE + k + 4];
        a[3] = As[(rbase + 8) * AS_STRIDE + k + 4];
#pragma unroll
        for (int nt = 0; nt < 8; nt++) {
            uint2 b = *(const uint2*)&g_w1f[((ksg * 16 + cg * 8 + nt) * 32 + lane) * 2];
            mma_tf32(d[nt], a, b.x, b.y);
        }
    }
    __syncthreads();   // all As reads done

    // ---- Epilogue 1: bias+relu -> tf32 h1 back into As ----
#pragma unroll
    for (int nt = 0; nt < 8; nt++) {
        int col = cg * 64 + nt * 8 + 2 * (lane & 3);
        int r0 = rg * 16 + (lane >> 2);
        float b0 = __ldg(&bias1[col]);
        float b1v = __ldg(&bias1[col + 1]);
        float v0 = fmaxf(d[nt][0] + b0, 0.f);
        float v1 = fmaxf(d[nt][1] + b1v, 0.f);
        float v2 = fmaxf(d[nt][2] + b0, 0.f);
        float v3 = fmaxf(d[nt][3] + b1v, 0.f);
        *(uint2*)&As[r0 * AS_STRIDE + col] = make_uint2(f2tf(v0), f2tf(v1));
        *(uint2*)&As[(r0 + 8) * AS_STRIDE + col] = make_uint2(f2tf(v2), f2tf(v3));
#pragma unroll
        for (int r = 0; r < 4; r++) d[nt][r] = 0.f;
    }
    __syncthreads();

    // ---- Phase 3: GEMM2 ----
#pragma unroll
    for (int ksg = 0; ksg < 16; ksg++) {
        int k = ksg * 8 + (lane & 3);
        unsigned a[4];
        a[0] = As[rbase * AS_STRIDE + k];
        a[1] = As[(rbase + 8) * AS_STRIDE + k];
        a[2] = As[rbase * AS_STRIDE + k + 4];
        a[3] = As[(rbase + 8) * AS_STRIDE + k + 4];
#pragma unroll
        for (int nt = 0; nt < 8; nt++) {
            uint2 b = *(const uint2*)&g_w2f[((ksg * 16 + cg * 8 + nt) * 32 + lane) * 2];
            mma_tf32(d[nt], a, b.x, b.y);
        }
    }

    // ---- Epilogue 2: bias+relu -> out + BN stats ----
#pragma unroll
    for (int nt = 0; nt < 8; nt++) {
        int col = cg * 64 + nt * 8 + 2 * (lane & 3);
        int r0 = row0 + rg * 16 + (lane >> 2);
        float b0 = __ldg(&bias2[col]);
        float b1v = __ldg(&bias2[col + 1]);
        float v0 = fmaxf(d[nt][0] + b0, 0.f);
        float v1 = fmaxf(d[nt][1] + b1v, 0.f);
        float v2 = fmaxf(d[nt][2] + b0, 0.f);
        float v3 = fmaxf(d[nt][3] + b1v, 0.f);
        bool ok0 = (r0 < N), ok1 = (r0 + 8 < N);
        if (ok0) *(float2*)&out[r0 * 128 + col] = make_float2(v0, v1);
        if (ok1) *(float2*)&out[(r0 + 8) * 128 + col] = make_float2(v2, v3);
        float s0 = (ok0 ? v0 : 0.f) + (ok1 ? v2 : 0.f);
        float s1 = (ok0 ? v1 : 0.f) + (ok1 ? v3 : 0.f);
        float q0 = (ok0 ? v0 * v0 : 0.f) + (ok1 ? v2 * v2 : 0.f);
        float q1 = (ok0 ? v1 * v1 : 0.f) + (ok1 ? v3 * v3 : 0.f);
#pragma unroll
        for (int m = 16; m >= 4; m >>= 1) {
            s0 += __shfl_xor_sync(0xffffffffu, s0, m);
            s1 += __shfl_xor_sync(0xffffffffu, s1, m);
            q0 += __shfl_xor_sync(0xffffffffu, q0, m);
            q1 += __shfl_xor_sync(0xffffffffu, q1, m);
        }
        if (lane < 4) {
            asm volatile("red.global.add.v2.f32 [%0], {%1, %2};"
                         :: "l"(&g_sum[col]), "f"(s0), "f"(s1) : "memory");
            asm volatile("red.global.add.v2.f32 [%0], {%1, %2};"
                         :: "l"(&g_sq[col]), "f"(q0), "f"(q1) : "memory");
        }
    }
}

// BN apply; per-block recompute of scale/shift from global sums.
__global__ void apply_bn_kernel(float4* __restrict__ out,
                                const float* __restrict__ gamma,
                                const float* __restrict__ beta,
                                float invN, int total4) {
    __shared__ float s_scale[GIN_H], s_shift[GIN_H];
    int t = threadIdx.x;
    if (t < GIN_H) {
        float mean = g_sum[t] * invN;
        float var = fmaf(-mean, mean, g_sq[t] * invN);
        float sc = gamma[t] * rsqrtf(var + 1e-5f);
        s_scale[t] = sc;
        s_shift[t] = fmaf(-mean, sc, beta[t]);
    }
    __syncthreads();
    int idx = blockIdx.x * blockDim.x + t;
    if (idx >= total4) return;
    int c = (idx & 31) * 4;
    float4 v = out[idx];
    v.x = fmaf(v.x, s_scale[c + 0], s_shift[c + 0]);
    v.y = fmaf(v.y, s_scale[c + 1], s_shift[c + 1]);
    v.z = fmaf(v.z, s_scale[c + 2], s_shift[c + 2]);
    v.w = fmaf(v.w, s_scale[c + 3], s_shift[c + 3]);
    out[idx] = v;
}

// ---------------------------------------------------------------------------
// Inputs: x, edge_index, edge_attr, W1, b1, W2, b2, gamma, beta
// ---------------------------------------------------------------------------
extern "C" void kernel_launch(void* const* d_in, const int* in_sizes, int n_in,
                              void* d_out, int out_size) {
    const float* x     = (const float*)d_in[0];
    const void*  ei    = d_in[1];
    const float* W1    = (const float*)d_in[3];
    const float* b1    = (const float*)d_in[4];
    const float* W2    = (const float*)d_in[5];
    const float* b2    = (const float*)d_in[6];
    const float* gamma = (const float*)d_in[7];
    const float* beta  = (const float*)d_in[8];
    float* out = (float*)d_out;

    int N = in_sizes[0] / GIN_H;
    int E = in_sizes[1] / 2;

    cudaFuncSetAttribute(fused_kernel,
                         cudaFuncAttributeMaxDynamicSharedMemorySize, FUSED_SMEM);

    int total4 = N * (GIN_H / 4);
    int eb = (E + 255) / 256;
    int nb = (N + SCAN_B - 1) / SCAN_B;

    zero_kernel<<<(N + 255) / 256, 256>>>((const unsigned*)ei, N);
    convert_kernel<<<(total4 + 255) / 256, 256>>>((const float4*)x, total4);
    wprep_kernel<<<32, 256>>>(W1, W2);
    hist_kernel<<<eb, 256>>>(ei, E);
    scan1_kernel<<<nb, SCAN_B>>>(N);
    scan2_kernel<<<1, 128>>>(nb);
    scan3_kernel<<<(N + 255) / 256, 256>>>(N, E);
    permute_kernel<<<eb, 256>>>(ei, E);

    int tiles = (N + 127) / 128;
    fused_kernel<<<tiles, 512, FUSED_SMEM>>>((const float4*)x, b1, b2, out, N);

    apply_bn_kernel<<<(total4 + 255) / 256, 256>>>((float4*)out, gamma, beta,
                                                   1.0f / (float)N, total4);
}

// round 11
// speedup vs baseline: 1.1092x; 1.1092x over previous
#include <cuda_runtime.h>
#include <cuda_fp16.h>

// ---------------------------------------------------------------------------
// GINBlock. R11 (resubmit of R10; container infra failed twice in a row):
//  - aggregate: warp/node CSR gather, MLP=8 batched loads, writes h0 as tf32
//  - mlp_kernel: GEMM1 -> smem -> GEMM2 fused (tf32 MMA, W in global frag
//    order), bias/relu/BN-stats epilogues
//  Keep: fp16 mirror, counting-sort CSR, parallel scan.
// ---------------------------------------------------------------------------

#define GIN_N_MAX 100000
#define GIN_H 128
#define GIN_E_MAX 3200000
#define SCAN_B 1024
#define SCAN_NB ((GIN_N_MAX + SCAN_B - 1) / SCAN_B)   // 98

__device__ __half   g_xh[GIN_N_MAX * GIN_H];       // fp16 mirror of x
__device__ __align__(16) unsigned g_h0t[GIN_N_MAX * GIN_H];  // h0 in tf32 bits
__device__ int      g_deg[GIN_N_MAX];
__device__ int      g_off[GIN_N_MAX + 1];
__device__ int      g_cursor[GIN_N_MAX];
__device__ int      g_srcs[GIN_E_MAX];
__device__ int      g_bsum[SCAN_NB];
__device__ int      g_boff[SCAN_NB];
__device__ __align__(16) unsigned g_w1f[16384];    // W1 tf32 fragment order
__device__ __align__(16) unsigned g_w2f[16384];    // W2 tf32 fragment order
__device__ __align__(16) float g_sum[GIN_H];
__device__ __align__(16) float g_sq[GIN_H];
__device__ int      g_is64;

__device__ __forceinline__ unsigned f2tf(float f) {
    unsigned r;
    asm("cvt.rna.tf32.f32 %0, %1;" : "=r"(r) : "f"(f));
    return r;
}
__device__ __forceinline__ void mma_tf32(float* d, const unsigned* a, unsigned b0, unsigned b1) {
    asm("mma.sync.aligned.m16n8k8.row.col.f32.tf32.tf32.f32 "
        "{%0,%1,%2,%3}, {%4,%5,%6,%7}, {%8,%9}, {%0,%1,%2,%3};"
        : "+f"(d[0]), "+f"(d[1]), "+f"(d[2]), "+f"(d[3])
        : "r"(a[0]), "r"(a[1]), "r"(a[2]), "r"(a[3]), "r"(b0), "r"(b1));
}

// zero deg + BN accums; thread 0 sniffs int64-vs-int32 edge_index.
__global__ void zero_kernel(const unsigned* __restrict__ ei, int N) {
    int idx = blockIdx.x * blockDim.x + threadIdx.x;
    if (idx < N) g_deg[idx] = 0;
    if (idx < GIN_H) { g_sum[idx] = 0.f; g_sq[idx] = 0.f; }
    if (idx == 0) {
        int allz = 1;
#pragma unroll
        for (int i = 0; i < 16; i++) allz &= (ei[2 * i + 1] == 0u);
        g_is64 = allz;
    }
}

// fp32 x -> fp16 mirror
__global__ void convert_kernel(const float4* __restrict__ x4, int total4) {
    int idx = blockIdx.x * blockDim.x + threadIdx.x;
    if (idx >= total4) return;
    float4 v = x4[idx];
    __half2 a = __floats2half2_rn(v.x, v.y);
    __half2 b = __floats2half2_rn(v.z, v.w);
    uint2 p;
    p.x = *(unsigned*)&a;
    p.y = *(unsigned*)&b;
    ((uint2*)g_xh)[idx] = p;
}

// Build W1/W2 tf32 fragment-order arrays in global.
__global__ void wprep_kernel(const float* __restrict__ W1,
                             const float* __restrict__ W2) {
    int s = blockIdx.x * blockDim.x + threadIdx.x;   // 0..8191
    if (s >= 8192) return;
    int l = s & 31, ntg = (s >> 5) & 15, ks = s >> 9;
    int k = ks * 8 + (l & 3);
    int n = ntg * 8 + (l >> 2);
    *(uint2*)&g_w1f[s * 2] = make_uint2(f2tf(__ldg(&W1[k * 128 + n])),
                                        f2tf(__ldg(&W1[(k + 4) * 128 + n])));
    *(uint2*)&g_w2f[s * 2] = make_uint2(f2tf(__ldg(&W2[k * 128 + n])),
                                        f2tf(__ldg(&W2[(k + 4) * 128 + n])));
}

__global__ void hist_kernel(const void* __restrict__ ei, int E) {
    int e = blockIdx.x * blockDim.x + threadIdx.x;
    if (e >= E) return;
    int d = g_is64 ? (int)__ldg(&((const long long*)ei)[E + e])
                   : __ldg(&((const int*)ei)[E + e]);
    atomicAdd(&g_deg[d], 1);
}

// ---- 3-phase exclusive scan ----
__global__ void __launch_bounds__(SCAN_B)
scan1_kernel(int N) {
    __shared__ int sh[SCAN_B];
    int t = threadIdx.x;
    int i = blockIdx.x * SCAN_B + t;
    int v = (i < N) ? g_deg[i] : 0;
    sh[t] = v;
    __syncthreads();
#pragma unroll
    for (int d = 1; d < SCAN_B; d <<= 1) {
        int u = (t >= d) ? sh[t - d] : 0;
        __syncthreads();
        sh[t] += u;
        __syncthreads();
    }
    if (i < N) g_off[i] = sh[t] - v;
    if (t == SCAN_B - 1) g_bsum[blockIdx.x] = sh[t];
}

__global__ void __launch_bounds__(128)
scan2_kernel(int NB) {
    __shared__ int sh[128];
    int t = threadIdx.x;
    int v = (t < NB) ? g_bsum[t] : 0;
    sh[t] = v;
    __syncthreads();
#pragma unroll
    for (int d = 1; d < 128; d <<= 1) {
        int u = (t >= d) ? sh[t - d] : 0;
        __syncthreads();
        sh[t] += u;
        __syncthreads();
    }
    if (t < NB) g_boff[t] = sh[t] - v;
}

__global__ void scan3_kernel(int N, int E) {
    int i = blockIdx.x * blockDim.x + threadIdx.x;
    if (i >= N) return;
    int v = g_off[i] + g_boff[i >> 10];
    g_off[i] = v;
    g_cursor[i] = v;
    if (i == 0) g_off[N] = E;
}

__global__ void permute_kernel(const void* __restrict__ ei, int E) {
    int e = blockIdx.x * blockDim.x + threadIdx.x;
    if (e >= E) return;
    int s, d;
    if (g_is64) {
        const long long* p = (const long long*)ei;
        s = (int)__ldg(&p[e]);
        d = (int)__ldg(&p[E + e]);
    } else {
        const int* p = (const int*)ei;
        s = __ldg(&p[e]);
        d = __ldg(&p[E + e]);
    }
    int pos = atomicAdd(&g_cursor[d], 1);
    g_srcs[pos] = s;
}

// Warp/node CSR gather; 8-wide load batches (MLP=8); writes h0 as tf32.
__global__ void aggregate_kernel(const float4* __restrict__ x4, int N) {
    int idx = blockIdx.x * blockDim.x + threadIdx.x;
    int node = idx >> 5;
    int lane = idx & 31;
    if (node >= N) return;
    float4 acc = x4[node * 32 + lane];
    const uint2* xh = (const uint2*)g_xh;
    int e = g_off[node], end = g_off[node + 1];
    while (e < end) {
        int cnt = min(32, end - e);
        int myidx = (lane < cnt) ? __ldg(&g_srcs[e + lane]) : 0;
        int j = 0;
        for (; j + 8 <= cnt; j += 8) {
            uint2 p[8];
#pragma unroll
            for (int q = 0; q < 8; q++) {
                int s = __shfl_sync(0xffffffffu, myidx, j + q);
                p[q] = __ldg(&xh[s * 32 + lane]);
            }
#pragma unroll
            for (int q = 0; q < 8; q++) {
                float2 f01 = __half22float2(*(__half2*)&p[q].x);
                float2 f23 = __half22float2(*(__half2*)&p[q].y);
                acc.x += f01.x; acc.y += f01.y;
                acc.z += f23.x; acc.w += f23.y;
            }
        }
        for (; j < cnt; j++) {
            int s = __shfl_sync(0xffffffffu, myidx, j);
            uint2 p = __ldg(&xh[s * 32 + lane]);
            float2 f01 = __half22float2(*(__half2*)&p.x);
            float2 f23 = __half22float2(*(__half2*)&p.y);
            acc.x += f01.x; acc.y += f01.y;
            acc.z += f23.x; acc.w += f23.y;
        }
        e += cnt;
    }
    ((uint4*)g_h0t)[node * 32 + lane] =
        make_uint4(f2tf(acc.x), f2tf(acc.y), f2tf(acc.z), f2tf(acc.w));
}

// ---------------------------------------------------------------------------
// Fused MLP: per 128-row tile: load tf32 h0 -> As -> GEMM1(+b1,relu) -> As
//            -> GEMM2(+b2,relu) -> out + BN stats.
// 512 threads = 16 warps; rg=wid>>1 (16-row group), cg=wid&1 (64-col group).
// ---------------------------------------------------------------------------
#define AS_STRIDE 132
#define MLP_SMEM (128 * AS_STRIDE * 4)     // 67584 B

__global__ void __launch_bounds__(512, 2)
mlp_kernel(const float* __restrict__ bias1,
           const float* __restrict__ bias2,
           float* __restrict__ out, int N) {
    extern __shared__ unsigned As[];         // [128][AS_STRIDE]
    const int tid = threadIdx.x;
    const int lane = tid & 31;
    const int wid = tid >> 5;
    const int row0 = blockIdx.x * 128;

    // stage tf32 h0 tile (coalesced uint4)
    const uint4* H04 = (const uint4*)g_h0t;
#pragma unroll
    for (int i = 0; i < 8; i++) {
        int s = i * 512 + tid;               // 0..4095
        int r = s >> 5, q = s & 31;
        uint4 v = make_uint4(0u, 0u, 0u, 0u);
        int gr = row0 + r;
        if (gr < N) v = H04[gr * 32 + q];
        *(uint4*)&As[r * AS_STRIDE + q * 4] = v;
    }
    __syncthreads();

    const int rg = wid >> 1, cg = wid & 1;
    float d[8][4];
#pragma unroll
    for (int nt = 0; nt < 8; nt++)
#pragma unroll
        for (int r = 0; r < 4; r++) d[nt][r] = 0.f;

    const int rbase = rg * 16 + (lane >> 2);
#pragma unroll
    for (int ksg = 0; ksg < 16; ksg++) {
        int k = ksg * 8 + (lane & 3);
        unsigned a[4];
        a[0] = As[rbase * AS_STRIDE + k];
        a[1] = As[(rbase + 8) * AS_STRIDE + k];
        a[2] = As[rbase * AS_STRIDE + k + 4];
        a[3] = As[(rbase + 8) * AS_STRIDE + k + 4];
#pragma unroll
        for (int nt = 0; nt < 8; nt++) {
            uint2 b = *(const uint2*)&g_w1f[((ksg * 16 + cg * 8 + nt) * 32 + lane) * 2];
            mma_tf32(d[nt], a, b.x, b.y);
        }
    }
    __syncthreads();

    // epilogue 1: bias+relu -> tf32 h1 back into As
#pragma unroll
    for (int nt = 0; nt < 8; nt++) {
        int col = cg * 64 + nt * 8 + 2 * (lane & 3);
        int r0 = rg * 16 + (lane >> 2);
        float b0 = __ldg(&bias1[col]);
        float b1v = __ldg(&bias1[col + 1]);
        float v0 = fmaxf(d[nt][0] + b0, 0.f);
        float v1 = fmaxf(d[nt][1] + b1v, 0.f);
        float v2 = fmaxf(d[nt][2] + b0, 0.f);
        float v3 = fmaxf(d[nt][3] + b1v, 0.f);
        *(uint2*)&As[r0 * AS_STRIDE + col] = make_uint2(f2tf(v0), f2tf(v1));
        *(uint2*)&As[(r0 + 8) * AS_STRIDE + col] = make_uint2(f2tf(v2), f2tf(v3));
#pragma unroll
        for (int r = 0; r < 4; r++) d[nt][r] = 0.f;
    }
    __syncthreads();

    // GEMM2
#pragma unroll
    for (int ksg = 0; ksg < 16; ksg++) {
        int k = ksg * 8 + (lane & 3);
        unsigned a[4];
        a[0] = As[rbase * AS_STRIDE + k];
        a[1] = As[(rbase + 8) * AS_STRIDE + k];
        a[2] = As[rbase * AS_STRIDE + k + 4];
        a[3] = As[(rbase + 8) * AS_STRIDE + k + 4];
#pragma unroll
        for (int nt = 0; nt < 8; nt++) {
            uint2 b = *(const uint2*)&g_w2f[((ksg * 16 + cg * 8 + nt) * 32 + lane) * 2];
            mma_tf32(d[nt], a, b.x, b.y);
        }
    }

    // epilogue 2: bias+relu -> out + BN stats
#pragma unroll
    for (int nt = 0; nt < 8; nt++) {
        int col = cg * 64 + nt * 8 + 2 * (lane & 3);
        int r0 = row0 + rg * 16 + (lane >> 2);
        float b0 = __ldg(&bias2[col]);
        float b1v = __ldg(&bias2[col + 1]);
        float v0 = fmaxf(d[nt][0] + b0, 0.f);
        float v1 = fmaxf(d[nt][1] + b1v, 0.f);
        float v2 = fmaxf(d[nt][2] + b0, 0.f);
        float v3 = fmaxf(d[nt][3] + b1v, 0.f);
        bool ok0 = (r0 < N), ok1 = (r0 + 8 < N);
        if (ok0) *(float2*)&out[r0 * 128 + col] = make_float2(v0, v1);
        if (ok1) *(float2*)&out[(r0 + 8) * 128 + col] = make_float2(v2, v3);
        float s0 = (ok0 ? v0 : 0.f) + (ok1 ? v2 : 0.f);
        float s1 = (ok0 ? v1 : 0.f) + (ok1 ? v3 : 0.f);
        float q0 = (ok0 ? v0 * v0 : 0.f) + (ok1 ? v2 * v2 : 0.f);
        float q1 = (ok0 ? v1 * v1 : 0.f) + (ok1 ? v3 * v3 : 0.f);
#pragma unroll
        for (int m = 16; m >= 4; m >>= 1) {
            s0 += __shfl_xor_sync(0xffffffffu, s0, m);
            s1 += __shfl_xor_sync(0xffffffffu, s1, m);
            q0 += __shfl_xor_sync(0xffffffffu, q0, m);
            q1 += __shfl_xor_sync(0xffffffffu, q1, m);
        }
        if (lane < 4) {
            asm volatile("red.global.add.v2.f32 [%0], {%1, %2};"
                         :: "l"(&g_sum[col]), "f"(s0), "f"(s1) : "memory");
            asm volatile("red.global.add.v2.f32 [%0], {%1, %2};"
                         :: "l"(&g_sq[col]), "f"(q0), "f"(q1) : "memory");
        }
    }
}

// BN apply; per-block recompute of scale/shift from global sums.
__global__ void apply_bn_kernel(float4* __restrict__ out,
                                const float* __restrict__ gamma,
                                const float* __restrict__ beta,
                                float invN, int total4) {
    __shared__ float s_scale[GIN_H], s_shift[GIN_H];
    int t = threadIdx.x;
    if (t < GIN_H) {
        float mean = g_sum[t] * invN;
        float var = fmaf(-mean, mean, g_sq[t] * invN);
        float sc = gamma[t] * rsqrtf(var + 1e-5f);
        s_scale[t] = sc;
        s_shift[t] = fmaf(-mean, sc, beta[t]);
    }
    __syncthreads();
    int idx = blockIdx.x * blockDim.x + t;
    if (idx >= total4) return;
    int c = (idx & 31) * 4;
    float4 v = out[idx];
    v.x = fmaf(v.x, s_scale[c + 0], s_shift[c + 0]);
    v.y = fmaf(v.y, s_scale[c + 1], s_shift[c + 1]);
    v.z = fmaf(v.z, s_scale[c + 2], s_shift[c + 2]);
    v.w = fmaf(v.w, s_scale[c + 3], s_shift[c + 3]);
    out[idx] = v;
}

// ---------------------------------------------------------------------------
// Inputs: x, edge_index, edge_attr, W1, b1, W2, b2, gamma, beta
// ---------------------------------------------------------------------------
extern "C" void kernel_launch(void* const* d_in, const int* in_sizes, int n_in,
                              void* d_out, int out_size) {
    const float* x     = (const float*)d_in[0];
    const void*  ei    = d_in[1];
    const float* W1    = (const float*)d_in[3];
    const float* b1    = (const float*)d_in[4];
    const float* W2    = (const float*)d_in[5];
    const float* b2    = (const float*)d_in[6];
    const float* gamma = (const float*)d_in[7];
    const float* beta  = (const float*)d_in[8];
    float* out = (float*)d_out;

    int N = in_sizes[0] / GIN_H;
    int E = in_sizes[1] / 2;

    cudaFuncSetAttribute(mlp_kernel,
                         cudaFuncAttributeMaxDynamicSharedMemorySize, MLP_SMEM);

    int total4 = N * (GIN_H / 4);
    int eb = (E + 255) / 256;
    int nb = (N + SCAN_B - 1) / SCAN_B;

    zero_kernel<<<(N + 255) / 256, 256>>>((const unsigned*)ei, N);
    convert_kernel<<<(total4 + 255) / 256, 256>>>((const float4*)x, total4);
    wprep_kernel<<<32, 256>>>(W1, W2);
    hist_kernel<<<eb, 256>>>(ei, E);
    scan1_kernel<<<nb, SCAN_B>>>(N);
    scan2_kernel<<<1, 128>>>(nb);
    scan3_kernel<<<(N + 255) / 256, 256>>>(N, E);
    permute_kernel<<<eb, 256>>>(ei, E);

    long long agg_items = (long long)N * 32;
    aggregate_kernel<<<(int)((agg_items + 255) / 256), 256>>>((const float4*)x, N);

    int tiles = (N + 127) / 128;
    mlp_kernel<<<tiles, 512, MLP_SMEM>>>(b1, b2, out, N);

    apply_bn_kernel<<<(total4 + 255) / 256, 256>>>((float4*)out, gamma, beta,
                                                   1.0f / (float)N, total4);
}